// round 9
// baseline (speedup 1.0000x reference)
#include <cuda_runtime.h>
#include <math.h>

// P2V: out[b,vox] = top2-margin of softmax_n( |s2| * exp(-|s1| * |xyz[b,:,n]-grid[:,vox]|^2) )
// margin = (exp(v0)-exp(v1)) / sum_n exp(v_n),  v_n in (0,1]
//
// v_n = 2^( kx0*g0 + kx1*g1 + kx2*g2 + p_n + lw_vox )   (one MUFU ex2 per n)
//   per-(b,n) table g_tab2[b][pair] = {kx0 pair, kx1 pair, kx2 pair, p pair} (32B rows)
//   lw = log2|s2| - s1*log2e*|g|^2  (per-voxel table {g0,g1,g2,lw})
// Sum of exp(v): deg-4 minimax poly, S=fma2(Q,v,S), +1024*c0 once.
// In-loop: MAX-ONLY exponent tracking (2 FMNMX/unit). Second max recovered by an
// exact epilogue rescan of the argmax lane's 32 values (bit-identical recompute),
// excluding one occurrence of the max.

typedef unsigned long long u64;

#define VOXN 32768
#define NN   1024

// [b][pair][ kx0_n, kx0_n1, kx1_n, kx1_n1, kx2_n, kx2_n1, p_n, p_n1 ]
__device__ __align__(256) float  g_tab2[4][512][8];
__device__ __align__(16)  float4 g_vox[VOXN];

__device__ __forceinline__ u64 pk2(float lo, float hi) {
    u64 r; asm("mov.b64 %0, {%1, %2};" : "=l"(r) : "f"(lo), "f"(hi)); return r;
}
__device__ __forceinline__ void upk2(u64 v, float& lo, float& hi) {
    asm("mov.b64 {%0, %1}, %2;" : "=f"(lo), "=f"(hi) : "l"(v));
}
__device__ __forceinline__ u64 fma2(u64 a, u64 b, u64 c) {
    u64 d; asm("fma.rn.f32x2 %0, %1, %2, %3;" : "=l"(d) : "l"(a), "l"(b), "l"(c)); return d;
}
__device__ __forceinline__ u64 add2(u64 a, u64 b) {
    u64 d; asm("add.rn.f32x2 %0, %1, %2;" : "=l"(d) : "l"(a), "l"(b)); return d;
}
__device__ __forceinline__ float ex2f(float x) {
    float r; asm("ex2.approx.ftz.f32 %0, %1;" : "=f"(r) : "f"(x)); return r;
}

// deg-4 minimax for e^x on [0,1], |err| ~ 3e-5
#define C4F 0.0695600f
#define C3F 0.1400096f
#define C2F 0.5099252f
#define C1F 0.9987378f
#define C0F 1.0000236f

// ---- fused prologue: blocks 0-127 per-voxel, blocks 128-143 per-(b,n) tables ----
__global__ void pv_prep(const float* __restrict__ xyz,
                        const float* __restrict__ grid,
                        const float* __restrict__ s1,
                        const float* __restrict__ s2) {
    const float L = 1.4426950408889634f;
    float s1a = fabsf(s1[0]);
    if (blockIdx.x < 128) {
        int vx = blockIdx.x * 256 + threadIdx.x;
        float g0 = grid[vx];
        float g1 = grid[VOXN + vx];
        float g2 = grid[2 * VOXN + vx];
        float lw = __log2f(fabsf(s2[0])) - s1a * L * (g0 * g0 + g1 * g1 + g2 * g2);
        g_vox[vx] = make_float4(g0, g1, g2, lw);
    } else {
        int i = (blockIdx.x - 128) * 256 + threadIdx.x;   // 0..4095
        if (i >= 4 * NN) return;
        int b = i >> 10, n = i & (NN - 1);
        float k = 2.0f * s1a * L;
        float x0 = xyz[b * 3 * NN + 0 * NN + n];
        float x1 = xyz[b * 3 * NN + 1 * NN + n];
        float x2 = xyz[b * 3 * NN + 2 * NN + n];
        int pr = n >> 1, h = n & 1;
        g_tab2[b][pr][0 + h] = k * x0;
        g_tab2[b][pr][2 + h] = k * x1;
        g_tab2[b][pr][4 + h] = k * x2;
        g_tab2[b][pr][6 + h] = -s1a * L * (x0 * x0 + x1 * x1 + x2 * x2);
    }
}

// ---- main: one warp -> 4 voxels x 2 batches = 8 outputs; block = 4 warps ----
__global__ void __launch_bounds__(128, 7) pv_main(float* __restrict__ out)
{
    int tid  = threadIdx.x;
    int lane = tid & 31;
    int wig  = tid >> 5;                     // 0..3
    int warp = blockIdx.x * 4 + wig;
    int vg   = warp >> 1;                    // voxel group (4 voxels)
    int bh   = warp & 1;                     // batches {2bh, 2bh+1}
    int vox0 = vg * 4;

    // per-voxel broadcast constants
    u64 G[4][3], LW[4];
    #pragma unroll
    for (int v = 0; v < 4; v++) {
        float4 gv = g_vox[vox0 + v];
        G[v][0] = pk2(gv.x, gv.x);
        G[v][1] = pk2(gv.y, gv.y);
        G[v][2] = pk2(gv.z, gv.z);
        LW[v]   = pk2(gv.w, gv.w);
    }

    const u64 Cq3 = pk2(C4F, C4F);
    const u64 Cq2 = pk2(C3F, C3F);
    const u64 Cq1 = pk2(C2F, C2F);
    const u64 Cq0 = pk2(C1F, C1F);

    u64 S[8];
    float m0[8];
    #pragma unroll
    for (int o = 0; o < 8; o++) { S[o] = 0ull; m0[o] = -1e30f; }

    // table pointer: u64 units. per-b stride = 512 pairs * 4 u64 = 2048.
    const u64* tp = reinterpret_cast<const u64*>(g_tab2) + (u64)(2 * bh) * 2048 + lane * 4;

    #pragma unroll 2
    for (int j = 0; j < 16; j++) {
        ulonglong2 a0 = reinterpret_cast<const ulonglong2*>(tp)[0];        // {kx0, kx1}
        ulonglong2 a1 = reinterpret_cast<const ulonglong2*>(tp)[1];        // {kx2, p}
        ulonglong2 b0 = reinterpret_cast<const ulonglong2*>(tp + 2048)[0];
        ulonglong2 b1 = reinterpret_cast<const ulonglong2*>(tp + 2048)[1];
        u64 X[2][4] = { { a0.x, a0.y, a1.x, a1.y }, { b0.x, b0.y, b1.x, b1.y } };

        #pragma unroll
        for (int v = 0; v < 4; v++) {
            #pragma unroll
            for (int bi = 0; bi < 2; bi++) {
                int o = v * 2 + bi;
                u64 acc = fma2(X[bi][0], G[v][0], add2(X[bi][3], LW[v]));
                acc = fma2(X[bi][1], G[v][1], acc);
                acc = fma2(X[bi][2], G[v][2], acc);
                float alo, ahi; upk2(acc, alo, ahi);
                u64 vv = pk2(ex2f(alo), ex2f(ahi));      // v in [0,1]
                // max-only exponent tracking (2 FMNMX, ALU pipe, in MUFU shadow)
                m0[o] = fmaxf(m0[o], fmaxf(alo, ahi));
                u64 q = fma2(Cq3, vv, Cq2);
                q = fma2(q, vv, Cq1);
                q = fma2(q, vv, Cq0);
                S[o] = fma2(q, vv, S[o]);
            }
        }
        tp += 128;
    }

    // ---- epilogue: per output, exact top-2 via max butterfly + argmax-lane rescan ----
    const float* gt = reinterpret_cast<const float*>(g_tab2);
    float res = 0.f;
    #pragma unroll
    for (int o = 0; o < 8; o++) {
        int v  = o >> 1;
        int bi = o & 1;
        int b  = 2 * bh + bi;

        // global max
        float M0 = m0[o];
        #pragma unroll
        for (int off = 16; off; off >>= 1)
            M0 = fmaxf(M0, __shfl_xor_sync(0xffffffffu, M0, off));

        // lane that owns the max
        unsigned am = __ballot_sync(0xffffffffu, m0[o] == M0);
        int argLane = __ffs(am) - 1;

        // rescan argLane's 32 values: lane l recomputes (pair = argLane + (l>>1)*32, half = l&1)
        float gv0, gv1, gv2, lwv;
        { float flo, fhi;
          upk2(G[v][0], gv0, fhi); upk2(G[v][1], gv1, fhi);
          upk2(G[v][2], gv2, fhi); upk2(LW[v], lwv, fhi); (void)flo; }
        int pr = argLane + (lane >> 1) * 32;
        const float* tf = gt + ((u64)b * 512 + pr) * 8 + (lane & 1);
        // bit-identical to the packed loop: ADD then 3 dependent FMAs
        float acc = fmaf(tf[0], gv0, __fadd_rn(tf[6], lwv));
        acc = fmaf(tf[2], gv1, acc);
        acc = fmaf(tf[4], gv2, acc);

        // exclude ONE occurrence of the max among the rescanned values
        unsigned em = __ballot_sync(0xffffffffu, acc == M0);
        int ex = em ? (__ffs(em) - 1) : -1;

        float cand = fmaxf((lane == argLane) ? -1e30f : m0[o],
                           (lane == ex)      ? -1e30f : acc);
        #pragma unroll
        for (int off = 16; off; off >>= 1)
            cand = fmaxf(cand, __shfl_xor_sync(0xffffffffu, cand, off));

        // sum reduction
        float slo, shi; upk2(S[o], slo, shi);
        float Sf = slo + shi;
        #pragma unroll
        for (int off = 16; off; off >>= 1)
            Sf += __shfl_xor_sync(0xffffffffu, Sf, off);

        if (lane == o) {
            float v0 = exp2f(M0), v1 = exp2f(cand);
            res = (__expf(v0) - __expf(v1)) / (Sf + 1024.0f * C0F);
        }
    }
    if (lane < 8) {
        int v = lane >> 1, bi = lane & 1;
        out[(2 * bh + bi) * VOXN + vox0 + v] = res;
    }
}

extern "C" void kernel_launch(void* const* d_in, const int* in_sizes, int n_in,
                              void* d_out, int out_size) {
    const float* xyz = nullptr; const float* grid = nullptr;
    const float* s1 = nullptr;  const float* s2 = nullptr;
    for (int i = 0; i < n_in; i++) {
        if (in_sizes[i] == 4 * 3 * NN)      xyz = (const float*)d_in[i];
        else if (in_sizes[i] == 3 * VOXN)   grid = (const float*)d_in[i];
        else if (in_sizes[i] == 1) { if (!s1) s1 = (const float*)d_in[i]; else s2 = (const float*)d_in[i]; }
    }
    float* out = (float*)d_out;

    pv_prep<<<144, 256>>>(xyz, grid, s1, s2);
    // 131072 outputs, 8 per warp -> 16384 warps -> 4096 blocks of 4 warps
    pv_main<<<4096, 128>>>(out);
}

// round 10
// speedup vs baseline: 1.0287x; 1.0287x over previous
#include <cuda_runtime.h>
#include <math.h>

// P2V: out[b,vox] = top2-margin of softmax_n( |s2| * exp(-|s1| * |xyz[b,:,n]-grid[:,vox]|^2) )
// margin = (exp(v0)-exp(v1)) / sum_n exp(v_n),  v_n in (0,1]
//
// v_n = 2^( kx0*g0 + kx1*g1 + kx2*g2 + p_n + lw_vox )   (one MUFU ex2 per n)
// Split pair-packed tables with 16B rows (4 L1 wavefronts per LDG.128):
//   T01[b][pair] = {kx0_n,kx0_n1, kx1_n,kx1_n1}
//   T23[b][pair] = {kx2_n,kx2_n1, p_n,  p_n1 }
//   lw = log2|s2| - s1*log2e*|g|^2  (per-voxel table {g0,g1,g2,lw})
// Sum of exp(v): deg-4 minimax poly (Estrin), S=fma2(Q,v,S), +1024*c0 once.
// Full top-2 tracked on the exponent acc (monotone) via scalar FMNMX (ALU pipe),
// exact exp2f/expf applied only to the final two values. Butterfly epilogue.

typedef unsigned long long u64;

#define VOXN 32768
#define NN   1024

__device__ __align__(256) float4 T01[4][512];   // [batch][pair] {kx0 pair, kx1 pair}
__device__ __align__(256) float4 T23[4][512];   // [batch][pair] {kx2 pair, p pair}
__device__ __align__(16)  float4 g_vox[VOXN];

__device__ __forceinline__ u64 pk2(float lo, float hi) {
    u64 r; asm("mov.b64 %0, {%1, %2};" : "=l"(r) : "f"(lo), "f"(hi)); return r;
}
__device__ __forceinline__ void upk2(u64 v, float& lo, float& hi) {
    asm("mov.b64 {%0, %1}, %2;" : "=f"(lo), "=f"(hi) : "l"(v));
}
__device__ __forceinline__ u64 fma2(u64 a, u64 b, u64 c) {
    u64 d; asm("fma.rn.f32x2 %0, %1, %2, %3;" : "=l"(d) : "l"(a), "l"(b), "l"(c)); return d;
}
__device__ __forceinline__ u64 add2(u64 a, u64 b) {
    u64 d; asm("add.rn.f32x2 %0, %1, %2;" : "=l"(d) : "l"(a), "l"(b)); return d;
}
__device__ __forceinline__ u64 mul2(u64 a, u64 b) {
    u64 d; asm("mul.rn.f32x2 %0, %1, %2;" : "=l"(d) : "l"(a), "l"(b)); return d;
}
__device__ __forceinline__ float ex2f(float x) {
    float r; asm("ex2.approx.ftz.f32 %0, %1;" : "=f"(r) : "f"(x)); return r;
}

// deg-4 minimax for e^x on [0,1], |err| ~ 3e-5
#define C4F 0.0695600f
#define C3F 0.1400096f
#define C2F 0.5099252f
#define C1F 0.9987378f
#define C0F 1.0000236f

// ---- fused prologue: blocks 0-127 per-voxel, blocks 128-143 per-(b,n) tables ----
__global__ void pv_prep(const float* __restrict__ xyz,
                        const float* __restrict__ grid,
                        const float* __restrict__ s1,
                        const float* __restrict__ s2) {
    const float L = 1.4426950408889634f;
    float s1a = fabsf(s1[0]);
    if (blockIdx.x < 128) {
        int vx = blockIdx.x * 256 + threadIdx.x;
        float g0 = grid[vx];
        float g1 = grid[VOXN + vx];
        float g2 = grid[2 * VOXN + vx];
        float lw = __log2f(fabsf(s2[0])) - s1a * L * (g0 * g0 + g1 * g1 + g2 * g2);
        g_vox[vx] = make_float4(g0, g1, g2, lw);
    } else {
        int i = (blockIdx.x - 128) * 256 + threadIdx.x;   // 0..4095
        if (i >= 4 * NN) return;
        int b = i >> 10, n = i & (NN - 1);
        float k = 2.0f * s1a * L;
        float x0 = xyz[b * 3 * NN + 0 * NN + n];
        float x1 = xyz[b * 3 * NN + 1 * NN + n];
        float x2 = xyz[b * 3 * NN + 2 * NN + n];
        int pr = n >> 1, h = n & 1;
        float* t01 = reinterpret_cast<float*>(&T01[b][pr]);
        float* t23 = reinterpret_cast<float*>(&T23[b][pr]);
        t01[0 + h] = k * x0;
        t01[2 + h] = k * x1;
        t23[0 + h] = k * x2;
        t23[2 + h] = -s1a * L * (x0 * x0 + x1 * x1 + x2 * x2);
    }
}

// ---- main: one warp -> 4 voxels x 2 batches = 8 outputs; block = 4 warps ----
__global__ void __launch_bounds__(128, 6) pv_main(float* __restrict__ out)
{
    int tid  = threadIdx.x;
    int lane = tid & 31;
    int wig  = tid >> 5;                     // 0..3
    int warp = blockIdx.x * 4 + wig;
    int vg   = warp >> 1;                    // voxel group (4 voxels)
    int bh   = warp & 1;                     // batches {2bh, 2bh+1}
    int vox0 = vg * 4;

    // per-voxel broadcast constants
    u64 G[4][3], LW[4];
    #pragma unroll
    for (int v = 0; v < 4; v++) {
        float4 gv = g_vox[vox0 + v];
        G[v][0] = pk2(gv.x, gv.x);
        G[v][1] = pk2(gv.y, gv.y);
        G[v][2] = pk2(gv.z, gv.z);
        LW[v]   = pk2(gv.w, gv.w);
    }

    const u64 Cq3 = pk2(C4F, C4F);
    const u64 Cq2 = pk2(C3F, C3F);
    const u64 Cq1 = pk2(C2F, C2F);
    const u64 Cq0 = pk2(C1F, C1F);

    u64 S[8];
    float m0[8], m1[8];
    #pragma unroll
    for (int o = 0; o < 8; o++) { S[o] = 0ull; m0[o] = -1e30f; m1[o] = -1e30f; }

    // 16B-row tables: lane-stride 16B -> 4 wavefronts per LDG.128
    const ulonglong2* p01 = reinterpret_cast<const ulonglong2*>(&T01[2 * bh][lane]);
    const ulonglong2* p23 = reinterpret_cast<const ulonglong2*>(&T23[2 * bh][lane]);

    #pragma unroll 2
    for (int j = 0; j < 16; j++) {
        ulonglong2 a01 = p01[j * 32];          // batch 2bh   {kx0, kx1}
        ulonglong2 a23 = p23[j * 32];          //             {kx2, p}
        ulonglong2 b01 = p01[j * 32 + 512];    // batch 2bh+1
        ulonglong2 b23 = p23[j * 32 + 512];
        u64 X[2][4] = { { a01.x, a01.y, a23.x, a23.y },
                        { b01.x, b01.y, b23.x, b23.y } };

        #pragma unroll
        for (int v = 0; v < 4; v++) {
            #pragma unroll
            for (int bi = 0; bi < 2; bi++) {
                int o = v * 2 + bi;
                u64 acc = fma2(X[bi][0], G[v][0], add2(X[bi][3], LW[v]));
                acc = fma2(X[bi][1], G[v][1], acc);
                acc = fma2(X[bi][2], G[v][2], acc);
                float alo, ahi; upk2(acc, alo, ahi);
                u64 vv = pk2(ex2f(alo), ex2f(ahi));      // v in [0,1]
                // full top-2 on exponent (ALU pipe, fills MUFU shadow)
                m1[o] = fmaxf(m1[o], fminf(m0[o], alo));
                m0[o] = fmaxf(m0[o], alo);
                m1[o] = fmaxf(m1[o], fminf(m0[o], ahi));
                m0[o] = fmaxf(m0[o], ahi);
                // deg-4 poly, Estrin (shorter chain): Q = (C4 v + C3) v^2 + (C2 v + C1)
                u64 v2 = mul2(vv, vv);
                u64 qa = fma2(Cq3, vv, Cq2);
                u64 qb = fma2(Cq1, vv, Cq0);
                u64 q  = fma2(qa, v2, qb);
                S[o] = fma2(q, vv, S[o]);
            }
        }
    }

    // cross-lane reduction per output (butterfly top-2 on exponents + sum)
    float res = 0.f;
    #pragma unroll
    for (int o = 0; o < 8; o++) {
        float slo, shi; upk2(S[o], slo, shi);
        float Sf = slo + shi;
        float M0 = m0[o], M1 = m1[o];
        #pragma unroll
        for (int off = 16; off; off >>= 1) {
            float o0 = __shfl_xor_sync(0xffffffffu, M0, off);
            float o1 = __shfl_xor_sync(0xffffffffu, M1, off);
            float os = __shfl_xor_sync(0xffffffffu, Sf, off);
            M1 = fmaxf(fmaxf(M1, o1), fminf(M0, o0));
            M0 = fmaxf(M0, o0);
            Sf += os;
        }
        if (lane == o) {
            float v0 = exp2f(M0), v1 = exp2f(M1);
            res = (__expf(v0) - __expf(v1)) / (Sf + 1024.0f * C0F);
        }
    }
    if (lane < 8) {
        int v = lane >> 1, bi = lane & 1;
        out[(2 * bh + bi) * VOXN + vox0 + v] = res;
    }
}

extern "C" void kernel_launch(void* const* d_in, const int* in_sizes, int n_in,
                              void* d_out, int out_size) {
    const float* xyz = nullptr; const float* grid = nullptr;
    const float* s1 = nullptr;  const float* s2 = nullptr;
    for (int i = 0; i < n_in; i++) {
        if (in_sizes[i] == 4 * 3 * NN)      xyz = (const float*)d_in[i];
        else if (in_sizes[i] == 3 * VOXN)   grid = (const float*)d_in[i];
        else if (in_sizes[i] == 1) { if (!s1) s1 = (const float*)d_in[i]; else s2 = (const float*)d_in[i]; }
    }
    float* out = (float*)d_out;

    pv_prep<<<144, 256>>>(xyz, grid, s1, s2);
    // 131072 outputs, 8 per warp -> 16384 warps -> 4096 blocks of 4 warps
    pv_main<<<4096, 128>>>(out);
}

// round 12
// speedup vs baseline: 1.2719x; 1.2363x over previous
#include <cuda_runtime.h>
#include <math.h>

// P2V: out[b,vox] = top2-margin of softmax_n( |s2| * exp(-|s1| * |xyz[b,:,n]-grid[:,vox]|^2) )
// margin = (exp(v0)-exp(v1)) / sum_n exp(v_n),  v_n in (0,1]
//
// v_n = 2^( kx0*g0 + kx1*g1 + kx2*g2 + p_n + lw_vox )   (one MUFU ex2 per n)
//   per-(b,n) table g_tab2[b][pair] = {kx0 pair, kx1 pair, kx2 pair, p pair} (32B rows)
//   lw = log2|s2| - s1*log2e*|g|^2  (per-voxel table {g0,g1,g2,lw})
// Sum of exp(v): deg-4 minimax poly (Horner, 4 fma2 incl. fused accumulation), +1024*c0 once.
// Top-2 tracked on the exponent acc (monotone) via scalar FMNMX (ALU pipe).
// Block epilogue (R8, race-free): partials -> padded smem, ONE warp serially
// reduces the block's 32 outputs.
// Single controlled change vs the 61.0us best: launch_bounds(128,7) -> 28 warps/SM.

typedef unsigned long long u64;

#define VOXN 32768
#define NN   1024

// [b][pair][ kx0_n, kx0_n1, kx1_n, kx1_n1, kx2_n, kx2_n1, p_n, p_n1 ]
__device__ __align__(256) float  g_tab2[4][512][8];
__device__ __align__(16)  float4 g_vox[VOXN];

__device__ __forceinline__ u64 pk2(float lo, float hi) {
    u64 r; asm("mov.b64 %0, {%1, %2};" : "=l"(r) : "f"(lo), "f"(hi)); return r;
}
__device__ __forceinline__ void upk2(u64 v, float& lo, float& hi) {
    asm("mov.b64 {%0, %1}, %2;" : "=f"(lo), "=f"(hi) : "l"(v));
}
__device__ __forceinline__ u64 fma2(u64 a, u64 b, u64 c) {
    u64 d; asm("fma.rn.f32x2 %0, %1, %2, %3;" : "=l"(d) : "l"(a), "l"(b), "l"(c)); return d;
}
__device__ __forceinline__ u64 add2(u64 a, u64 b) {
    u64 d; asm("add.rn.f32x2 %0, %1, %2;" : "=l"(d) : "l"(a), "l"(b)); return d;
}
__device__ __forceinline__ float ex2f(float x) {
    float r; asm("ex2.approx.ftz.f32 %0, %1;" : "=f"(r) : "f"(x)); return r;
}

// deg-4 minimax for e^x on [0,1], |err| ~ 3e-5
#define C4F 0.0695600f
#define C3F 0.1400096f
#define C2F 0.5099252f
#define C1F 0.9987378f
#define C0F 1.0000236f

// ---- fused prologue: blocks 0-127 per-voxel, blocks 128-143 per-(b,n) tables ----
__global__ void pv_prep(const float* __restrict__ xyz,
                        const float* __restrict__ grid,
                        const float* __restrict__ s1,
                        const float* __restrict__ s2) {
    const float L = 1.4426950408889634f;
    float s1a = fabsf(s1[0]);
    if (blockIdx.x < 128) {
        int vx = blockIdx.x * 256 + threadIdx.x;
        float g0 = grid[vx];
        float g1 = grid[VOXN + vx];
        float g2 = grid[2 * VOXN + vx];
        float lw = __log2f(fabsf(s2[0])) - s1a * L * (g0 * g0 + g1 * g1 + g2 * g2);
        g_vox[vx] = make_float4(g0, g1, g2, lw);
    } else {
        int i = (blockIdx.x - 128) * 256 + threadIdx.x;   // 0..4095
        if (i >= 4 * NN) return;
        int b = i >> 10, n = i & (NN - 1);
        float k = 2.0f * s1a * L;
        float x0 = xyz[b * 3 * NN + 0 * NN + n];
        float x1 = xyz[b * 3 * NN + 1 * NN + n];
        float x2 = xyz[b * 3 * NN + 2 * NN + n];
        int pr = n >> 1, h = n & 1;
        g_tab2[b][pr][0 + h] = k * x0;
        g_tab2[b][pr][2 + h] = k * x1;
        g_tab2[b][pr][4 + h] = k * x2;
        g_tab2[b][pr][6 + h] = -s1a * L * (x0 * x0 + x1 * x1 + x2 * x2);
    }
}

// ---- main: one warp -> 4 voxels x 2 batches = 8 outputs; block = 4 warps ----
__global__ void __launch_bounds__(128, 7) pv_main(float* __restrict__ out)
{
    __shared__ float sm0[32][33];
    __shared__ float sm1[32][33];
    __shared__ float sS[32][33];

    int tid  = threadIdx.x;
    int lane = tid & 31;
    int wig  = tid >> 5;                     // 0..3
    int warp = blockIdx.x * 4 + wig;
    int vg   = warp >> 1;                    // voxel group (4 voxels)
    int bh   = warp & 1;                     // batches {2bh, 2bh+1}
    int vox0 = vg * 4;

    // per-voxel broadcast constants
    u64 G[4][3], LW[4];
    #pragma unroll
    for (int v = 0; v < 4; v++) {
        float4 gv = g_vox[vox0 + v];
        G[v][0] = pk2(gv.x, gv.x);
        G[v][1] = pk2(gv.y, gv.y);
        G[v][2] = pk2(gv.z, gv.z);
        LW[v]   = pk2(gv.w, gv.w);
    }

    const u64 Cq3 = pk2(C4F, C4F);
    const u64 Cq2 = pk2(C3F, C3F);
    const u64 Cq1 = pk2(C2F, C2F);
    const u64 Cq0 = pk2(C1F, C1F);

    u64 S[8];
    float m0[8], m1[8];
    #pragma unroll
    for (int o = 0; o < 8; o++) { S[o] = 0ull; m0[o] = -1e30f; m1[o] = -1e30f; }

    // table pointer: u64 units. per-b stride = 512 pairs * 4 u64 = 2048.
    const u64* tp = reinterpret_cast<const u64*>(g_tab2) + (u64)(2 * bh) * 2048 + lane * 4;

    #pragma unroll 2
    for (int j = 0; j < 16; j++) {
        ulonglong2 a0 = reinterpret_cast<const ulonglong2*>(tp)[0];        // {kx0, kx1}
        ulonglong2 a1 = reinterpret_cast<const ulonglong2*>(tp)[1];        // {kx2, p}
        ulonglong2 b0 = reinterpret_cast<const ulonglong2*>(tp + 2048)[0];
        ulonglong2 b1 = reinterpret_cast<const ulonglong2*>(tp + 2048)[1];
        u64 X[2][4] = { { a0.x, a0.y, a1.x, a1.y }, { b0.x, b0.y, b1.x, b1.y } };

        #pragma unroll
        for (int v = 0; v < 4; v++) {
            #pragma unroll
            for (int bi = 0; bi < 2; bi++) {
                int o = v * 2 + bi;
                u64 acc = fma2(X[bi][0], G[v][0], add2(X[bi][3], LW[v]));
                acc = fma2(X[bi][1], G[v][1], acc);
                acc = fma2(X[bi][2], G[v][2], acc);
                float alo, ahi; upk2(acc, alo, ahi);
                // issue MUFU early...
                u64 vv = pk2(ex2f(alo), ex2f(ahi));      // v in [0,1]
                // ...top-2 on exponent (ALU pipe) fills the MUFU shadow
                m1[o] = fmaxf(m1[o], fminf(m0[o], alo));
                m0[o] = fmaxf(m0[o], alo);
                m1[o] = fmaxf(m1[o], fminf(m0[o], ahi));
                m0[o] = fmaxf(m0[o], ahi);
                // Horner deg-4 with fused accumulation (4 fma2 total)
                u64 q = fma2(Cq3, vv, Cq2);
                q = fma2(q, vv, Cq1);
                q = fma2(q, vv, Cq0);
                S[o] = fma2(q, vv, S[o]);
            }
        }
        tp += 128;
    }

    // dump per-lane partials to smem (one row per output, padded stride 33)
    #pragma unroll
    for (int o = 0; o < 8; o++) {
        float slo, shi; upk2(S[o], slo, shi);
        int outid = wig * 8 + o;
        sm0[outid][lane] = m0[o];
        sm1[outid][lane] = m1[o];
        sS[outid][lane]  = slo + shi;
    }
    __syncthreads();

    // one warp reduces all 32 outputs of the block (race-free serial scan)
    if (tid < 32) {
        int t = tid;                         // output id within block
        float M0 = -1e30f, M1 = -1e30f, Sf = 0.f;
        #pragma unroll
        for (int l = 0; l < 32; l++) {
            float a = sm0[t][l];
            float b = sm1[t][l];
            M1 = fmaxf(fmaxf(M1, b), fminf(M0, a));
            M0 = fmaxf(M0, a);
            Sf += sS[t][l];
        }
        float v0 = exp2f(M0), v1 = exp2f(M1);
        float res = (__expf(v0) - __expf(v1)) / (Sf + 1024.0f * C0F);

        int w  = t >> 3;                     // warp in block
        int o  = t & 7;
        int wr = blockIdx.x * 4 + w;
        int vgr = wr >> 1, bhr = wr & 1;
        int v  = o >> 1, bi = o & 1;
        out[(2 * bhr + bi) * VOXN + vgr * 4 + v] = res;
    }
}

extern "C" void kernel_launch(void* const* d_in, const int* in_sizes, int n_in,
                              void* d_out, int out_size) {
    const float* xyz = nullptr; const float* grid = nullptr;
    const float* s1 = nullptr;  const float* s2 = nullptr;
    for (int i = 0; i < n_in; i++) {
        if (in_sizes[i] == 4 * 3 * NN)      xyz = (const float*)d_in[i];
        else if (in_sizes[i] == 3 * VOXN)   grid = (const float*)d_in[i];
        else if (in_sizes[i] == 1) { if (!s1) s1 = (const float*)d_in[i]; else s2 = (const float*)d_in[i]; }
    }
    float* out = (float*)d_out;

    pv_prep<<<144, 256>>>(xyz, grid, s1, s2);
    // 131072 outputs, 8 per warp -> 16384 warps -> 4096 blocks of 4 warps
    pv_main<<<4096, 128>>>(out);
}